// round 9
// baseline (speedup 1.0000x reference)
#include <cuda_runtime.h>
#include <cstdint>

// Problem dims (fixed)
#define TSEQ 4096
#define CIN  2048
#define NF   2048
#define QKVN 6144
#define NEGV -1e30f

// GEMM tiling: CTA 256x128, 8 warps (4x2), warp tile 64x64
#define BMA 256
#define BN  128
#define BK  32
#define PADK 36                      // smem row stride (floats)
#define NSTAGE 3
#define TILE_A_FLOATS (BMA * PADK)
#define TILE_B_FLOATS (BN  * PADK)
#define TILE_A_BYTES  (TILE_A_FLOATS * 4)
#define TILE_B_BYTES  (TILE_B_FLOATS * 4)
#define BUF_BYTES     (TILE_A_BYTES + TILE_B_BYTES)     // 55296
#define DYN_SMEM      (NSTAGE * BUF_BYTES)              // 165888

// Scratch (device globals — allocation is forbidden; zero-initialized at load)
__device__ float g_qkv[(size_t)TSEQ * QKVN];   // 96 MB  [T][3*NF] (q|k|v), tf32-valued
__device__ float g_att[(size_t)TSEQ * TSEQ];   // 64 MB  att / probs
__device__ float g_WT [(size_t)QKVN * CIN];    // 48 MB  W^T, tf32-valued
__device__ float g_vT [(size_t)NF   * TSEQ];   // 32 MB  v^T, tf32-valued
__device__ float g_xr [(size_t)TSEQ * CIN];    // 32 MB  x rounded to tf32

// ---------------------------------------------------------------------------
// helpers
// ---------------------------------------------------------------------------
__device__ __forceinline__ uint32_t f2tf32(float f) {
    uint32_t u;
    asm("cvt.rna.tf32.f32 %0, %1;" : "=r"(u) : "f"(f));
    return u;
}
__device__ __forceinline__ float rnd_tf32(float f) { return __uint_as_float(f2tf32(f)); }

__device__ __forceinline__ uint32_t smem_u32(const void* p) {
    uint32_t a;
    asm("{ .reg .u64 t; cvta.to.shared.u64 t, %1; cvt.u32.u64 %0, t; }" : "=r"(a) : "l"(p));
    return a;
}

#define CP16(sa, gp) asm volatile("cp.async.cg.shared.global [%0], [%1], 16;" :: "r"(sa), "l"(gp))
#define CP_COMMIT()  asm volatile("cp.async.commit_group;" ::: "memory")
#define CP_WAIT(n)   asm volatile("cp.async.wait_group %0;" :: "n"(n) : "memory")

#define MMA_TF32(d, a0, a1, a2, a3, b0, b1) \
    asm volatile("mma.sync.aligned.m16n8k8.row.col.f32.tf32.tf32.f32 " \
        "{%0,%1,%2,%3}, {%4,%5,%6,%7}, {%8,%9}, {%0,%1,%2,%3};" \
        : "+f"((d)[0]), "+f"((d)[1]), "+f"((d)[2]), "+f"((d)[3]) \
        : "r"(a0), "r"(a1), "r"(a2), "r"(a3), "r"(b0), "r"(b1))

__device__ __forceinline__ void ldsm4(uint32_t* r, uint32_t addr) {
    asm volatile("ldmatrix.sync.aligned.m8n8.x4.shared.b16 {%0,%1,%2,%3}, [%4];"
                 : "=r"(r[0]), "=r"(r[1]), "=r"(r[2]), "=r"(r[3]) : "r"(addr));
}

// ---------------------------------------------------------------------------
// Staging: A tile 256x32 (8 x 16B per thread), B tile 128x32 (4 x 16B).
// ---------------------------------------------------------------------------
__device__ __forceinline__ void stage_cp_A(const float* __restrict__ g, int ld, int k0,
                                           uint32_t sbase, int tid) {
#pragma unroll
    for (int j = 0; j < 8; j++) {
        const int idx = tid + 256 * j;
        const int r = idx >> 3, c = (idx & 7) << 2;
        CP16(sbase + (uint32_t)(r * PADK + c) * 4u, g + (size_t)r * ld + k0 + c);
    }
}
__device__ __forceinline__ void stage_cp_B(const float* __restrict__ g, int ld, int k0,
                                           uint32_t sbase, int tid) {
#pragma unroll
    for (int j = 0; j < 4; j++) {
        const int idx = tid + 256 * j;
        const int r = idx >> 3, c = (idx & 7) << 2;
        CP16(sbase + (uint32_t)(r * PADK + c) * 4u, g + (size_t)r * ld + k0 + c);
    }
}

// ---------------------------------------------------------------------------
// Compute one K-chunk: warp tile 64x64 = 4 mt x 8 nt m16n8 tiles.
// Per kk: 4 A-ldsm.x4 + 4 B-ldsm.x4, 32 MMA.
// ---------------------------------------------------------------------------
__device__ __forceinline__ void compute_chunk(uint32_t sA, uint32_t sB,
                                              const uint32_t aoff[4], const uint32_t boff[4],
                                              float acc[4][8][4]) {
#pragma unroll
    for (int kk = 0; kk < 4; kk++) {
        const uint32_t kb = (uint32_t)kk * 32u;      // 8 floats per kk
        uint32_t afr[4][4], bfr[4][4];
#pragma unroll
        for (int mt = 0; mt < 4; mt++) ldsm4(afr[mt], sA + aoff[mt] + kb);
#pragma unroll
        for (int p = 0; p < 4; p++) ldsm4(bfr[p], sB + boff[p] + kb);
#pragma unroll
        for (int mt = 0; mt < 4; mt++)
#pragma unroll
            for (int nt = 0; nt < 8; nt++)
                MMA_TF32(acc[mt][nt],
                         afr[mt][0], afr[mt][1], afr[mt][2], afr[mt][3],
                         bfr[nt >> 1][(nt & 1) * 2], bfr[nt >> 1][(nt & 1) * 2 + 1]);
    }
}

// ---------------------------------------------------------------------------
// Mainloop: acc += A(256xK) @ B(128xK)^T over nk chunks of 32.
// ---------------------------------------------------------------------------
__device__ __forceinline__ void gemm_mainloop(const float* __restrict__ A, int lda,
                                              const float* __restrict__ B, int ldb,
                                              int kStart, int nk, float* smem,
                                              float acc[4][8][4], int tid) {
    const int lane = tid & 31, warp = tid >> 5;
    const int wm = warp >> 1, wn = warp & 1;
    const uint32_t s0 = smem_u32(smem);

    // ldmatrix lane address offsets (bytes, tile-relative)
    const int q = lane >> 3, qr = lane & 7;
    uint32_t aoff[4], boff[4];
#pragma unroll
    for (int mt = 0; mt < 4; mt++)
        aoff[mt] = (uint32_t)(((wm * 64 + mt * 16 + (q & 1) * 8 + qr) * PADK + (q >> 1) * 4) * 4);
#pragma unroll
    for (int p = 0; p < 4; p++)
        boff[p] = (uint32_t)(((wn * 64 + p * 16 + ((q >> 1) & 1) * 8 + qr) * PADK + (q & 1) * 4) * 4);

#pragma unroll
    for (int s = 0; s < NSTAGE - 1; s++) {
        if (s < nk) {
            const uint32_t sb = s0 + (uint32_t)s * BUF_BYTES;
            stage_cp_A(A, lda, kStart + s * BK, sb, tid);
            stage_cp_B(B, ldb, kStart + s * BK, sb + TILE_A_BYTES, tid);
        }
        CP_COMMIT();
    }

    for (int i = 0; i < nk; i++) {
        CP_WAIT(NSTAGE - 2);
        __syncthreads();
        if (i + NSTAGE - 1 < nk) {
            const int s = (i + NSTAGE - 1) % NSTAGE;
            const uint32_t sb = s0 + (uint32_t)s * BUF_BYTES;
            stage_cp_A(A, lda, kStart + (i + NSTAGE - 1) * BK, sb, tid);
            stage_cp_B(B, ldb, kStart + (i + NSTAGE - 1) * BK, sb + TILE_A_BYTES, tid);
        }
        CP_COMMIT();
        const uint32_t sA = s0 + (uint32_t)(i % NSTAGE) * BUF_BYTES;
        compute_chunk(sA, sA + TILE_A_BYTES, aoff, boff, acc);
    }
}

// Epilogue coords: row = rowBase + wm*64 + mt*16 + (lane>>2) (+8 for d2,d3);
//                  col = colBase + wn*64 + nt*8 + (lane&3)*2

// ---------------------------------------------------------------------------
// GEMM 1: qkv = xr @ WT^T + b   grid (48, 16)
// ---------------------------------------------------------------------------
__global__ __launch_bounds__(256, 1) void k_qkv_tc(const float* __restrict__ bias) {
    extern __shared__ float smem[];
    const int tid = threadIdx.x;
    const int bx = blockIdx.x, by = blockIdx.y;
    float acc[4][8][4] = {};
    gemm_mainloop(g_xr + (size_t)by * BMA * CIN, CIN,
                  g_WT + (size_t)bx * BN * CIN, CIN, 0, CIN / BK, smem, acc, tid);

    const int lane = tid & 31, warp = tid >> 5;
    const int wm = warp >> 1, wn = warp & 1;
#pragma unroll
    for (int mt = 0; mt < 4; mt++) {
        const int r0 = by * BMA + wm * 64 + mt * 16 + (lane >> 2);
#pragma unroll
        for (int nt = 0; nt < 8; nt++) {
            const int col = bx * BN + wn * 64 + nt * 8 + (lane & 3) * 2;
            const float b0 = bias[col], b1 = bias[col + 1];
            *(float2*)(g_qkv + (size_t)r0 * QKVN + col) =
                make_float2(rnd_tf32(acc[mt][nt][0] + b0), rnd_tf32(acc[mt][nt][1] + b1));
            *(float2*)(g_qkv + (size_t)(r0 + 8) * QKVN + col) =
                make_float2(rnd_tf32(acc[mt][nt][2] + b0), rnd_tf32(acc[mt][nt][3] + b1));
        }
    }
}

// ---------------------------------------------------------------------------
// GEMM 2: att = mask(q @ k^T * scale)  grid (32, 16); 256-row x 128-col tiles
// ---------------------------------------------------------------------------
__global__ __launch_bounds__(256, 1) void k_att_tc(const int* __restrict__ npadd_p) {
    extern __shared__ float smem[];
    const int tid = threadIdx.x;
    const int bx = blockIdx.x, by = blockIdx.y;
    const int rowMax = by * BMA + BMA - 1;
    const int colMin = bx * BN, colMax = colMin + BN - 1;
    if (colMin > rowMax) return;                 // fully above diagonal: never read
    const int n_padd = *npadd_p;
    if (rowMax < n_padd) return;                 // all-padding rows: never read
    if (colMax < n_padd) {                       // all-padding cols: NEG fill
        const float4 negv = make_float4(NEGV, NEGV, NEGV, NEGV);
        for (int i = tid; i < BMA * BN / 4; i += 256) {
            int m = i >> 5, n = (i & 31) << 2;
            *(float4*)(g_att + (size_t)(by * BMA + m) * TSEQ + colMin + n) = negv;
        }
        return;
    }

    float acc[4][8][4] = {};
    gemm_mainloop(g_qkv + (size_t)by * BMA * QKVN, QKVN,
                  g_qkv + (size_t)bx * BN * QKVN + NF, QKVN, 0, NF / BK, smem, acc, tid);

    const float scale = 0.022097086912079608f;  // 1/sqrt(2048)
    const int lane = tid & 31, warp = tid >> 5;
    const int wm = warp >> 1, wn = warp & 1;
#pragma unroll
    for (int mt = 0; mt < 4; mt++) {
        const int r0 = by * BMA + wm * 64 + mt * 16 + (lane >> 2);
        const int r1 = r0 + 8;
#pragma unroll
        for (int nt = 0; nt < 8; nt++) {
            const int col = bx * BN + wn * 64 + nt * 8 + (lane & 3) * 2;
            float2 o0, o1;
            o0.x = (r0 >= n_padd && col     <= r0 && col     >= n_padd) ? acc[mt][nt][0] * scale : NEGV;
            o0.y = (r0 >= n_padd && col + 1 <= r0 && col + 1 >= n_padd) ? acc[mt][nt][1] * scale : NEGV;
            o1.x = (r1 >= n_padd && col     <= r1 && col     >= n_padd) ? acc[mt][nt][2] * scale : NEGV;
            o1.y = (r1 >= n_padd && col + 1 <= r1 && col + 1 >= n_padd) ? acc[mt][nt][3] * scale : NEGV;
            *(float2*)(g_att + (size_t)r0 * TSEQ + col) = o0;
            *(float2*)(g_att + (size_t)r1 * TSEQ + col) = o1;
        }
    }
}

// ---------------------------------------------------------------------------
// GEMM 3: y = p @ vT^T   grid (16, 16); K in [n_padd&~31, (by+1)*256)
// Heavy row-blocks launch first (by reversed). Softmax guarantees p == 0 on
// [cap, blockEnd) and on padding rows, so the causal K-cap stays exact.
// ---------------------------------------------------------------------------
__global__ __launch_bounds__(256, 1) void k_out_tc(float* __restrict__ Y,
                                                   const int* __restrict__ npadd_p) {
    extern __shared__ float smem[];
    const int tid = threadIdx.x;
    const int bx = blockIdx.x;
    const int by = (gridDim.y - 1) - blockIdx.y;    // heavy first
    const int n_padd = *npadd_p;
    const int kStart = n_padd & ~(BK - 1);
    const int nk = ((by + 1) * BMA - kStart) / BK;

    float acc[4][8][4] = {};
    gemm_mainloop(g_att + (size_t)by * BMA * TSEQ, TSEQ,
                  g_vT + (size_t)bx * BN * TSEQ, TSEQ, kStart, nk, smem, acc, tid);

    const int lane = tid & 31, warp = tid >> 5;
    const int wm = warp >> 1, wn = warp & 1;
#pragma unroll
    for (int mt = 0; mt < 4; mt++) {
        const int r0 = by * BMA + wm * 64 + mt * 16 + (lane >> 2);
#pragma unroll
        for (int nt = 0; nt < 8; nt++) {
            const int col = bx * BN + wn * 64 + nt * 8 + (lane & 3) * 2;
            *(float2*)(Y + (size_t)r0 * NF + col) =
                make_float2(acc[mt][nt][0], acc[mt][nt][1]);
            *(float2*)(Y + (size_t)(r0 + 8) * NF + col) =
                make_float2(acc[mt][nt][2], acc[mt][nt][3]);
        }
    }
}

// ---------------------------------------------------------------------------
// Transpose + round: dst[c][r] = tf32(src[r][c])
// ---------------------------------------------------------------------------
__global__ void k_transpose(const float* __restrict__ src, float* __restrict__ dst,
                            int lds, int ldd) {
    __shared__ float t[32][33];
    const int bx = blockIdx.x * 32, by = blockIdx.y * 32;
    const int x = threadIdx.x, y = threadIdx.y;
#pragma unroll
    for (int j = 0; j < 32; j += 8)
        t[y + j][x] = rnd_tf32(src[(size_t)(by + y + j) * lds + bx + x]);
    __syncthreads();
#pragma unroll
    for (int j = 0; j < 32; j += 8)
        dst[(size_t)(bx + y + j) * ldd + by + x] = t[x][y + j];
}

// Round-copy: g_xr = tf32(x)
__global__ void k_roundcpy(const float* __restrict__ src, float* __restrict__ dst, int n4) {
    int i = blockIdx.x * blockDim.x + threadIdx.x;
    if (i < n4) {
        float4 v = ((const float4*)src)[i];
        v.x = rnd_tf32(v.x); v.y = rnd_tf32(v.y);
        v.z = rnd_tf32(v.z); v.w = rnd_tf32(v.w);
        ((float4*)dst)[i] = v;
    }
}

// ---------------------------------------------------------------------------
// Row softmax over the causal prefix [0, cap), cap = ceil128(r+1).
// Also zeroes [cap, capz) where capz = ceil256(r+1) (k_out's block K-range),
// and the whole [0, capz) for padding rows, so GEMM3 reads only valid zeros.
// ---------------------------------------------------------------------------
__global__ __launch_bounds__(256) void k_softmax(const int* __restrict__ npadd_p) {
    const int r = blockIdx.x;
    const int n_padd = *npadd_p;
    const int cap  = ((r >> 7) + 1) << 7;   // 128-aligned causal prefix end
    const int capz = ((r >> 8) + 1) << 8;   // 256-aligned k_out block end
    float* row = g_att + (size_t)r * TSEQ;
    const int tid = threadIdx.x;
    if (r < n_padd) {
        for (int c = tid * 4; c < capz; c += 256 * 4)
            *(float4*)(row + c) = make_float4(0.f, 0.f, 0.f, 0.f);
        return;
    }
    __shared__ float redmax[8], redsum[8];
    float vals[16];
    float mx = NEGV;
#pragma unroll
    for (int i = 0; i < 16; i++) {
        const int c = tid + i * 256;
        vals[i] = (c < cap) ? row[c] : NEGV;
        mx = fmaxf(mx, vals[i]);
    }
#pragma unroll
    for (int o = 16; o > 0; o >>= 1) mx = fmaxf(mx, __shfl_xor_sync(0xffffffffu, mx, o));
    if ((tid & 31) == 0) redmax[tid >> 5] = mx;
    __syncthreads();
    mx = redmax[0];
#pragma unroll
    for (int i = 1; i < 8; i++) mx = fmaxf(mx, redmax[i]);
    float s = 0.f;
#pragma unroll
    for (int i = 0; i < 16; i++) {
        vals[i] = __expf(vals[i] - mx);    // underflows to 0 for masked entries
        s += vals[i];
    }
#pragma unroll
    for (int o = 16; o > 0; o >>= 1) s += __shfl_xor_sync(0xffffffffu, s, o);
    if ((tid & 31) == 0) redsum[tid >> 5] = s;
    __syncthreads();
    s = redsum[0];
#pragma unroll
    for (int i = 1; i < 8; i++) s += redsum[i];
    const float inv = 1.f / s;
#pragma unroll
    for (int i = 0; i < 16; i++) {
        const int c = tid + i * 256;
        if (c < cap) row[c] = rnd_tf32(vals[i] * inv);
    }
    // zero the slack [cap, capz) read by GEMM3's 256-wide K blocks
    for (int c = cap + tid * 4; c < capz; c += 256 * 4)
        *(float4*)(row + c) = make_float4(0.f, 0.f, 0.f, 0.f);
}

// ---------------------------------------------------------------------------
extern "C" void kernel_launch(void* const* d_in, const int* in_sizes, int n_in,
                              void* d_out, int out_size) {
    const float* x  = (const float*)d_in[0];
    const float* W  = (const float*)d_in[1];
    const float* b  = (const float*)d_in[2];
    const int* npad = (const int*)d_in[3];
    float* y = (float*)d_out;

    cudaFuncSetAttribute(k_qkv_tc, cudaFuncAttributeMaxDynamicSharedMemorySize, DYN_SMEM);
    cudaFuncSetAttribute(k_att_tc, cudaFuncAttributeMaxDynamicSharedMemorySize, DYN_SMEM);
    cudaFuncSetAttribute(k_out_tc, cudaFuncAttributeMaxDynamicSharedMemorySize, DYN_SMEM);

    float *wt_p, *vt_p, *qkv_p, *xr_p;
    cudaGetSymbolAddress((void**)&wt_p, g_WT);
    cudaGetSymbolAddress((void**)&vt_p, g_vT);
    cudaGetSymbolAddress((void**)&qkv_p, g_qkv);
    cudaGetSymbolAddress((void**)&xr_p, g_xr);

    dim3 tb(32, 8);
    const int nx4 = TSEQ * CIN / 4;
    k_roundcpy<<<(nx4 + 255) / 256, 256>>>(x, xr_p, nx4);
    // W (2048 x 6144) -> WT (6144 x 2048), rounded
    k_transpose<<<dim3(QKVN / 32, CIN / 32), tb>>>(W, wt_p, QKVN, CIN);
    k_qkv_tc<<<dim3(QKVN / BN, TSEQ / BMA), 256, DYN_SMEM>>>(b);
    // v = qkv[:, 2NF:] (4096 x 2048) -> vT (2048 x 4096)
    k_transpose<<<dim3(NF / 32, TSEQ / 32), tb>>>(qkv_p + 2 * NF, vt_p, QKVN, TSEQ);
    k_att_tc<<<dim3(TSEQ / BN, TSEQ / BMA), 256, DYN_SMEM>>>(npad);
    k_softmax<<<TSEQ, 256>>>(npad);
    k_out_tc<<<dim3(NF / BN, TSEQ / BMA), 256, DYN_SMEM>>>(y, npad);
}

// round 10
// speedup vs baseline: 1.2095x; 1.2095x over previous
#include <cuda_runtime.h>
#include <cstdint>

// Problem dims (fixed)
#define TSEQ 4096
#define CIN  2048
#define NF   2048
#define QKVN 6144
#define NEGV -1e30f

// GEMM tiling (R8 proven config): CTA 128x128, 8 warps (4x2), warp 32x64
#define BM 128
#define BN 128
#define BK 32
#define PADK 36                      // smem row stride (floats)
#define NSTAGE 3
#define TILE_FLOATS (BM * PADK)
#define TILE_BYTES  (TILE_FLOATS * 4)
#define BUF_BYTES   (2 * TILE_BYTES)               // A + B per stage
#define DYN_SMEM    (NSTAGE * BUF_BYTES)           // 110592 B

// Scratch (device globals — allocation is forbidden; zero-initialized at load)
__device__ float g_qkv[(size_t)TSEQ * QKVN];   // 96 MB  [T][3*NF] (q|k|v), tf32-valued
__device__ float g_att[(size_t)TSEQ * TSEQ];   // 64 MB  att / probs
__device__ float g_WT [(size_t)QKVN * CIN];    // 48 MB  W^T, tf32-valued
__device__ float g_vT [(size_t)NF   * TSEQ];   // 32 MB  v^T, tf32-valued
__device__ float g_xr [(size_t)TSEQ * CIN];    // 32 MB  x rounded to tf32

// ---------------------------------------------------------------------------
// helpers
// ---------------------------------------------------------------------------
__device__ __forceinline__ uint32_t f2tf32(float f) {
    uint32_t u;
    asm("cvt.rna.tf32.f32 %0, %1;" : "=r"(u) : "f"(f));
    return u;
}
__device__ __forceinline__ float rnd_tf32(float f) { return __uint_as_float(f2tf32(f)); }

__device__ __forceinline__ uint32_t smem_u32(const void* p) {
    uint32_t a;
    asm("{ .reg .u64 t; cvta.to.shared.u64 t, %1; cvt.u32.u64 %0, t; }" : "=r"(a) : "l"(p));
    return a;
}

#define CP16(sa, gp) asm volatile("cp.async.cg.shared.global [%0], [%1], 16;" :: "r"(sa), "l"(gp))
#define CP_COMMIT()  asm volatile("cp.async.commit_group;" ::: "memory")
#define CP_WAIT(n)   asm volatile("cp.async.wait_group %0;" :: "n"(n) : "memory")

#define MMA_TF32(d, a0, a1, a2, a3, b0, b1) \
    asm volatile("mma.sync.aligned.m16n8k8.row.col.f32.tf32.tf32.f32 " \
        "{%0,%1,%2,%3}, {%4,%5,%6,%7}, {%8,%9}, {%0,%1,%2,%3};" \
        : "+f"((d)[0]), "+f"((d)[1]), "+f"((d)[2]), "+f"((d)[3]) \
        : "r"(a0), "r"(a1), "r"(a2), "r"(a3), "r"(b0), "r"(b1))

__device__ __forceinline__ void ldsm4(uint32_t* r, uint32_t addr) {
    asm volatile("ldmatrix.sync.aligned.m8n8.x4.shared.b16 {%0,%1,%2,%3}, [%4];"
                 : "=r"(r[0]), "=r"(r[1]), "=r"(r[2]), "=r"(r[3]) : "r"(addr));
}

// ---------------------------------------------------------------------------
// Stage one 128x32 fp32 tile (K-major) into smem via cp.async.
// ---------------------------------------------------------------------------
__device__ __forceinline__ void stage_cp(const float* __restrict__ g, int ld, int k0,
                                         uint32_t sbase, int tid) {
#pragma unroll
    for (int j = 0; j < 4; j++) {
        const int idx = tid + 256 * j;
        const int r = idx >> 3, c = (idx & 7) << 2;
        CP16(sbase + (uint32_t)(r * PADK + c) * 4u, g + (size_t)r * ld + k0 + c);
    }
}

// ---------------------------------------------------------------------------
// Compute one K-chunk via ldmatrix fragment loads (warp tile 32x64).
// ---------------------------------------------------------------------------
__device__ __forceinline__ void compute_chunk(uint32_t sA, uint32_t sB,
                                              const uint32_t aoff[2], const uint32_t boff[4],
                                              float acc[2][8][4]) {
#pragma unroll
    for (int kk = 0; kk < 4; kk++) {
        const uint32_t kb = (uint32_t)kk * 32u;      // 8 floats per kk
        uint32_t afr[2][4], bfr[4][4];
        ldsm4(afr[0], sA + aoff[0] + kb);
        ldsm4(afr[1], sA + aoff[1] + kb);
#pragma unroll
        for (int p = 0; p < 4; p++) ldsm4(bfr[p], sB + boff[p] + kb);
#pragma unroll
        for (int mt = 0; mt < 2; mt++)
#pragma unroll
            for (int nt = 0; nt < 8; nt++)
                MMA_TF32(acc[mt][nt],
                         afr[mt][0], afr[mt][1], afr[mt][2], afr[mt][3],
                         bfr[nt >> 1][(nt & 1) * 2], bfr[nt >> 1][(nt & 1) * 2 + 1]);
    }
}

// ---------------------------------------------------------------------------
// Mainloop: acc += A(128xK) @ B(128xK)^T over nk chunks of 32.
// ---------------------------------------------------------------------------
__device__ __forceinline__ void gemm_mainloop(const float* __restrict__ A, int lda,
                                              const float* __restrict__ B, int ldb,
                                              int kStart, int nk, float* smem,
                                              float acc[2][8][4], int tid) {
    const int lane = tid & 31, warp = tid >> 5;
    const int wm = warp >> 1, wn = warp & 1;
    const uint32_t s0 = smem_u32(smem);

    const int q = lane >> 3, qr = lane & 7;
    uint32_t aoff[2], boff[4];
#pragma unroll
    for (int mt = 0; mt < 2; mt++)
        aoff[mt] = (uint32_t)(((wm * 32 + mt * 16 + (q & 1) * 8 + qr) * PADK + (q >> 1) * 4) * 4);
#pragma unroll
    for (int p = 0; p < 4; p++)
        boff[p] = (uint32_t)(((wn * 64 + p * 16 + ((q >> 1) & 1) * 8 + qr) * PADK + (q & 1) * 4) * 4);

#pragma unroll
    for (int s = 0; s < NSTAGE - 1; s++) {
        if (s < nk) {
            const uint32_t sb = s0 + (uint32_t)s * BUF_BYTES;
            stage_cp(A, lda, kStart + s * BK, sb, tid);
            stage_cp(B, ldb, kStart + s * BK, sb + TILE_BYTES, tid);
        }
        CP_COMMIT();
    }

    for (int i = 0; i < nk; i++) {
        CP_WAIT(NSTAGE - 2);
        __syncthreads();
        if (i + NSTAGE - 1 < nk) {
            const int s = (i + NSTAGE - 1) % NSTAGE;
            const uint32_t sb = s0 + (uint32_t)s * BUF_BYTES;
            stage_cp(A, lda, kStart + (i + NSTAGE - 1) * BK, sb, tid);
            stage_cp(B, ldb, kStart + (i + NSTAGE - 1) * BK, sb + TILE_BYTES, tid);
        }
        CP_COMMIT();
        const uint32_t sA = s0 + (uint32_t)(i % NSTAGE) * BUF_BYTES;
        compute_chunk(sA, sA + TILE_BYTES, aoff, boff, acc);
    }
}

// Epilogue coords: row0 = wm*32+mt*16+(lane>>2), row1=row0+8;
//                  col = wn*64+nt*8+(lane&3)*2

// ---------------------------------------------------------------------------
// GEMM 1 (split): qkv[:, colBase:colBase+gridDim.x*BN] = xr @ WT^T + b
// Skips all-padding row blocks (their q/k never read; v multiplies p==0 and
// unwritten zero-init scratch stays zero).
// ---------------------------------------------------------------------------
__global__ __launch_bounds__(256, 2) void k_qkv_tc(const float* __restrict__ bias,
                                                   const int* __restrict__ npadd_p,
                                                   int colBase) {
    extern __shared__ float smem[];
    const int tid = threadIdx.x;
    const int bx = blockIdx.x, by = blockIdx.y;
    if ((by + 1) * BM <= *npadd_p) return;
    float acc[2][8][4] = {};
    gemm_mainloop(g_xr + (size_t)by * BM * CIN, CIN,
                  g_WT + (size_t)(colBase + bx * BN) * CIN, CIN, 0, CIN / BK, smem, acc, tid);

    const int lane = tid & 31, warp = tid >> 5;
    const int wm = warp >> 1, wn = warp & 1;
#pragma unroll
    for (int mt = 0; mt < 2; mt++) {
        const int r0 = by * BM + wm * 32 + mt * 16 + (lane >> 2);
#pragma unroll
        for (int nt = 0; nt < 8; nt++) {
            const int col = colBase + bx * BN + wn * 64 + nt * 8 + (lane & 3) * 2;
            const float b0 = bias[col], b1 = bias[col + 1];
            *(float2*)(g_qkv + (size_t)r0 * QKVN + col) =
                make_float2(rnd_tf32(acc[mt][nt][0] + b0), rnd_tf32(acc[mt][nt][1] + b1));
            *(float2*)(g_qkv + (size_t)(r0 + 8) * QKVN + col) =
                make_float2(rnd_tf32(acc[mt][nt][2] + b0), rnd_tf32(acc[mt][nt][3] + b1));
        }
    }
}

// ---------------------------------------------------------------------------
// GEMM 2: att = mask(q @ k^T * scale)  grid (32, 32)
// ---------------------------------------------------------------------------
__global__ __launch_bounds__(256, 2) void k_att_tc(const int* __restrict__ npadd_p) {
    extern __shared__ float smem[];
    const int tid = threadIdx.x;
    const int bx = blockIdx.x, by = blockIdx.y;
    if (bx > by) return;
    const int n_padd = *npadd_p;
    const int rowMax = by * BM + BM - 1;
    const int colMin = bx * BN, colMax = colMin + BN - 1;
    if (rowMax < n_padd) return;
    if (colMax < n_padd) {
        const float4 negv = make_float4(NEGV, NEGV, NEGV, NEGV);
        for (int i = tid; i < BM * BN / 4; i += 256) {
            int m = i >> 5, n = (i & 31) << 2;
            *(float4*)(g_att + (size_t)(by * BM + m) * TSEQ + colMin + n) = negv;
        }
        return;
    }

    float acc[2][8][4] = {};
    gemm_mainloop(g_qkv + (size_t)by * BM * QKVN, QKVN,
                  g_qkv + (size_t)bx * BN * QKVN + NF, QKVN, 0, NF / BK, smem, acc, tid);

    const float scale = 0.022097086912079608f;  // 1/sqrt(2048)
    const int lane = tid & 31, warp = tid >> 5;
    const int wm = warp >> 1, wn = warp & 1;
#pragma unroll
    for (int mt = 0; mt < 2; mt++) {
        const int r0 = by * BM + wm * 32 + mt * 16 + (lane >> 2);
        const int r1 = r0 + 8;
#pragma unroll
        for (int nt = 0; nt < 8; nt++) {
            const int col = bx * BN + wn * 64 + nt * 8 + (lane & 3) * 2;
            float2 o0, o1;
            o0.x = (r0 >= n_padd && col     <= r0 && col     >= n_padd) ? acc[mt][nt][0] * scale : NEGV;
            o0.y = (r0 >= n_padd && col + 1 <= r0 && col + 1 >= n_padd) ? acc[mt][nt][1] * scale : NEGV;
            o1.x = (r1 >= n_padd && col     <= r1 && col     >= n_padd) ? acc[mt][nt][2] * scale : NEGV;
            o1.y = (r1 >= n_padd && col + 1 <= r1 && col + 1 >= n_padd) ? acc[mt][nt][3] * scale : NEGV;
            *(float2*)(g_att + (size_t)r0 * TSEQ + col) = o0;
            *(float2*)(g_att + (size_t)r1 * TSEQ + col) = o1;
        }
    }
}

// ---------------------------------------------------------------------------
// GEMM 3: y = p @ vT^T   grid (16, 32); K in [n_padd&~31, (by+1)*128)
// Heavy row-blocks first (by reversed) to kill the tail wave.
// ---------------------------------------------------------------------------
__global__ __launch_bounds__(256, 2) void k_out_tc(float* __restrict__ Y,
                                                   const int* __restrict__ npadd_p) {
    extern __shared__ float smem[];
    const int tid = threadIdx.x;
    const int bx = blockIdx.x;
    const int by = (gridDim.y - 1) - blockIdx.y;    // heavy first
    const int n_padd = *npadd_p;
    const int kStart = n_padd & ~(BK - 1);
    const int nk = ((by + 1) * BM - kStart) / BK;

    if (nk <= 0) {
        const float4 z = make_float4(0.f, 0.f, 0.f, 0.f);
        for (int i = tid; i < BM * BN / 4; i += 256) {
            int m = i >> 5, n = (i & 31) << 2;
            *(float4*)(Y + (size_t)(by * BM + m) * NF + bx * BN + n) = z;
        }
        return;
    }

    float acc[2][8][4] = {};
    gemm_mainloop(g_att + (size_t)by * BM * TSEQ, TSEQ,
                  g_vT + (size_t)bx * BN * TSEQ, TSEQ, kStart, nk, smem, acc, tid);

    const int lane = tid & 31, warp = tid >> 5;
    const int wm = warp >> 1, wn = warp & 1;
#pragma unroll
    for (int mt = 0; mt < 2; mt++) {
        const int r0 = by * BM + wm * 32 + mt * 16 + (lane >> 2);
#pragma unroll
        for (int nt = 0; nt < 8; nt++) {
            const int col = bx * BN + wn * 64 + nt * 8 + (lane & 3) * 2;
            *(float2*)(Y + (size_t)r0 * NF + col) =
                make_float2(acc[mt][nt][0], acc[mt][nt][1]);
            *(float2*)(Y + (size_t)(r0 + 8) * NF + col) =
                make_float2(acc[mt][nt][2], acc[mt][nt][3]);
        }
    }
}

// ---------------------------------------------------------------------------
// Transpose + round: dst[c][r] = tf32(src[r][c])
// ---------------------------------------------------------------------------
__global__ void k_transpose(const float* __restrict__ src, float* __restrict__ dst,
                            int lds, int ldd) {
    __shared__ float t[32][33];
    const int bx = blockIdx.x * 32, by = blockIdx.y * 32;
    const int x = threadIdx.x, y = threadIdx.y;
#pragma unroll
    for (int j = 0; j < 32; j += 8)
        t[y + j][x] = rnd_tf32(src[(size_t)(by + y + j) * lds + bx + x]);
    __syncthreads();
#pragma unroll
    for (int j = 0; j < 32; j += 8)
        dst[(size_t)(bx + y + j) * ldd + by + x] = t[x][y + j];
}

// Round-copy: g_xr = tf32(x)
__global__ void k_roundcpy(const float* __restrict__ src, float* __restrict__ dst, int n4) {
    int i = blockIdx.x * blockDim.x + threadIdx.x;
    if (i < n4) {
        float4 v = ((const float4*)src)[i];
        v.x = rnd_tf32(v.x); v.y = rnd_tf32(v.y);
        v.z = rnd_tf32(v.z); v.w = rnd_tf32(v.w);
        ((float4*)dst)[i] = v;
    }
}

// ---------------------------------------------------------------------------
// Row softmax over the causal prefix [0, cap), cap = ceil128(r+1).
// ---------------------------------------------------------------------------
__global__ __launch_bounds__(256) void k_softmax(const int* __restrict__ npadd_p) {
    const int r = blockIdx.x;
    const int n_padd = *npadd_p;
    const int cap = ((r >> 7) + 1) << 7;       // multiple of 128, > r
    float* row = g_att + (size_t)r * TSEQ;
    const int tid = threadIdx.x;
    if (r < n_padd) {
        for (int c = tid * 4; c < cap; c += 256 * 4)
            *(float4*)(row + c) = make_float4(0.f, 0.f, 0.f, 0.f);
        return;
    }
    __shared__ float redmax[8], redsum[8];
    float vals[16];
    float mx = NEGV;
#pragma unroll
    for (int i = 0; i < 16; i++) {
        const int c = tid + i * 256;
        vals[i] = (c < cap) ? row[c] : NEGV;
        mx = fmaxf(mx, vals[i]);
    }
#pragma unroll
    for (int o = 16; o > 0; o >>= 1) mx = fmaxf(mx, __shfl_xor_sync(0xffffffffu, mx, o));
    if ((tid & 31) == 0) redmax[tid >> 5] = mx;
    __syncthreads();
    mx = redmax[0];
#pragma unroll
    for (int i = 1; i < 8; i++) mx = fmaxf(mx, redmax[i]);
    float s = 0.f;
#pragma unroll
    for (int i = 0; i < 16; i++) {
        vals[i] = __expf(vals[i] - mx);    // underflows to 0 for masked entries
        s += vals[i];
    }
#pragma unroll
    for (int o = 16; o > 0; o >>= 1) s += __shfl_xor_sync(0xffffffffu, s, o);
    if ((tid & 31) == 0) redsum[tid >> 5] = s;
    __syncthreads();
    s = redsum[0];
#pragma unroll
    for (int i = 1; i < 8; i++) s += redsum[i];
    const float inv = 1.f / s;
#pragma unroll
    for (int i = 0; i < 16; i++) {
        const int c = tid + i * 256;
        if (c < cap) row[c] = rnd_tf32(vals[i] * inv);
    }
}

// ---------------------------------------------------------------------------
extern "C" void kernel_launch(void* const* d_in, const int* in_sizes, int n_in,
                              void* d_out, int out_size) {
    const float* x  = (const float*)d_in[0];
    const float* W  = (const float*)d_in[1];
    const float* b  = (const float*)d_in[2];
    const int* npad = (const int*)d_in[3];
    float* y = (float*)d_out;

    cudaFuncSetAttribute(k_qkv_tc, cudaFuncAttributeMaxDynamicSharedMemorySize, DYN_SMEM);
    cudaFuncSetAttribute(k_att_tc, cudaFuncAttributeMaxDynamicSharedMemorySize, DYN_SMEM);
    cudaFuncSetAttribute(k_out_tc, cudaFuncAttributeMaxDynamicSharedMemorySize, DYN_SMEM);

    // One-time stream/event creation (host-side only; no device allocation).
    static cudaStream_t sV = nullptr;
    static cudaEvent_t evFork = nullptr, evJoin = nullptr;
    if (sV == nullptr) {
        cudaStreamCreateWithFlags(&sV, cudaStreamNonBlocking);
        cudaEventCreateWithFlags(&evFork, cudaEventDisableTiming);
        cudaEventCreateWithFlags(&evJoin, cudaEventDisableTiming);
    }

    float *wt_p, *vt_p, *qkv_p, *xr_p;
    cudaGetSymbolAddress((void**)&wt_p, g_WT);
    cudaGetSymbolAddress((void**)&vt_p, g_vT);
    cudaGetSymbolAddress((void**)&qkv_p, g_qkv);
    cudaGetSymbolAddress((void**)&xr_p, g_xr);

    dim3 tb(32, 8);
    const int nx4 = TSEQ * CIN / 4;
    const cudaStream_t s0 = 0;

    // Main stream: round x, transpose W
    k_roundcpy<<<(nx4 + 255) / 256, 256, 0, s0>>>(x, xr_p, nx4);
    k_transpose<<<dim3(QKVN / 32, CIN / 32), tb, 0, s0>>>(W, wt_p, QKVN, CIN);
    cudaEventRecord(evFork, s0);

    // Side stream: v-columns of qkv + v transpose (needed only by k_out)
    cudaStreamWaitEvent(sV, evFork, 0);
    k_qkv_tc<<<dim3((QKVN - 2 * NF) / BN, TSEQ / BM), 256, DYN_SMEM, sV>>>(b, npad, 2 * NF);
    k_transpose<<<dim3(NF / 32, TSEQ / 32), tb, 0, sV>>>(qkv_p + 2 * NF, vt_p, QKVN, TSEQ);
    cudaEventRecord(evJoin, sV);

    // Main stream: qk-columns, att, softmax
    k_qkv_tc<<<dim3(2 * NF / BN, TSEQ / BM), 256, DYN_SMEM, s0>>>(b, npad, 0);
    k_att_tc<<<dim3(TSEQ / BN, TSEQ / BM), 256, DYN_SMEM, s0>>>(npad);
    k_softmax<<<TSEQ, 256, 0, s0>>>(npad);

    // Join: k_out needs vT
    cudaStreamWaitEvent(s0, evJoin, 0);
    k_out_tc<<<dim3(NF / BN, TSEQ / BM), 256, DYN_SMEM, s0>>>(y, npad);
}

// round 14
// speedup vs baseline: 1.2172x; 1.0063x over previous
#include <cuda_runtime.h>
#include <cstdint>

// Problem dims (fixed)
#define TSEQ 4096
#define CIN  2048
#define NF   2048
#define QKVN 6144
#define NEGV -1e30f

// GEMM tiling: CTA 128x128, 4 warps (2x2), warp tile 64x64, 128 threads
#define BM 128
#define BN 128
#define BK 32
#define NT 128                       // threads per GEMM CTA
#define PADK 36                      // smem row stride (floats)
#define NSTAGE 3
#define TILE_FLOATS (BM * PADK)
#define TILE_BYTES  (TILE_FLOATS * 4)
#define BUF_BYTES   (2 * TILE_BYTES)               // A + B per stage
#define DYN_SMEM    (NSTAGE * BUF_BYTES)           // 110592 B

// Scratch (device globals — allocation is forbidden; zero-initialized at load)
__device__ float g_qkv[(size_t)TSEQ * QKVN];   // 96 MB  [T][3*NF] (q|k|v), tf32-valued
__device__ float g_att[(size_t)TSEQ * TSEQ];   // 64 MB  att / probs
__device__ float g_WT [(size_t)QKVN * CIN];    // 48 MB  W^T, tf32-valued
__device__ float g_vT [(size_t)NF   * TSEQ];   // 32 MB  v^T, tf32-valued
__device__ float g_xr [(size_t)TSEQ * CIN];    // 32 MB  x rounded to tf32

// ---------------------------------------------------------------------------
// helpers
// ---------------------------------------------------------------------------
__device__ __forceinline__ uint32_t f2tf32(float f) {
    uint32_t u;
    asm("cvt.rna.tf32.f32 %0, %1;" : "=r"(u) : "f"(f));
    return u;
}
__device__ __forceinline__ float rnd_tf32(float f) { return __uint_as_float(f2tf32(f)); }

__device__ __forceinline__ uint32_t smem_u32(const void* p) {
    uint32_t a;
    asm("{ .reg .u64 t; cvta.to.shared.u64 t, %1; cvt.u32.u64 %0, t; }" : "=r"(a) : "l"(p));
    return a;
}

#define CP16(sa, gp) asm volatile("cp.async.cg.shared.global [%0], [%1], 16;" :: "r"(sa), "l"(gp))
#define CP_COMMIT()  asm volatile("cp.async.commit_group;" ::: "memory")
#define CP_WAIT(n)   asm volatile("cp.async.wait_group %0;" :: "n"(n) : "memory")

#define MMA_TF32(d, a0, a1, a2, a3, b0, b1) \
    asm volatile("mma.sync.aligned.m16n8k8.row.col.f32.tf32.tf32.f32 " \
        "{%0,%1,%2,%3}, {%4,%5,%6,%7}, {%8,%9}, {%0,%1,%2,%3};" \
        : "+f"((d)[0]), "+f"((d)[1]), "+f"((d)[2]), "+f"((d)[3]) \
        : "r"(a0), "r"(a1), "r"(a2), "r"(a3), "r"(b0), "r"(b1))

__device__ __forceinline__ void ldsm4(uint32_t* r, uint32_t addr) {
    asm volatile("ldmatrix.sync.aligned.m8n8.x4.shared.b16 {%0,%1,%2,%3}, [%4];"
                 : "=r"(r[0]), "=r"(r[1]), "=r"(r[2]), "=r"(r[3]) : "r"(addr));
}

// ---------------------------------------------------------------------------
// Stage one 128x32 fp32 tile (K-major) into smem via cp.async. 128 threads,
// 8 x 16B per thread.
// ---------------------------------------------------------------------------
__device__ __forceinline__ void stage_cp(const float* __restrict__ g, int ld, int k0,
                                         uint32_t sbase, int tid) {
#pragma unroll
    for (int j = 0; j < 8; j++) {
        const int idx = tid + NT * j;
        const int r = idx >> 3, c = (idx & 7) << 2;
        CP16(sbase + (uint32_t)(r * PADK + c) * 4u, g + (size_t)r * ld + k0 + c);
    }
}

// ---------------------------------------------------------------------------
// Compute one K-chunk (warp tile 64x64): per kk, 4 A-ldsm.x4 + 4 B-ldsm.x4,
// then 32 MMAs.
// ---------------------------------------------------------------------------
__device__ __forceinline__ void compute_chunk(uint32_t sA, uint32_t sB,
                                              const uint32_t aoff[4], const uint32_t boff[4],
                                              float acc[4][8][4]) {
#pragma unroll
    for (int kk = 0; kk < 4; kk++) {
        const uint32_t kb = (uint32_t)kk * 32u;      // 8 floats per kk
        uint32_t afr[4][4], bfr[4][4];
#pragma unroll
        for (int mt = 0; mt < 4; mt++) ldsm4(afr[mt], sA + aoff[mt] + kb);
#pragma unroll
        for (int p = 0; p < 4; p++) ldsm4(bfr[p], sB + boff[p] + kb);
#pragma unroll
        for (int mt = 0; mt < 4; mt++)
#pragma unroll
            for (int nt = 0; nt < 8; nt++)
                MMA_TF32(acc[mt][nt],
                         afr[mt][0], afr[mt][1], afr[mt][2], afr[mt][3],
                         bfr[nt >> 1][(nt & 1) * 2], bfr[nt >> 1][(nt & 1) * 2 + 1]);
    }
}

// ---------------------------------------------------------------------------
// Mainloop: acc += A(128xK) @ B(128xK)^T over nk chunks of 32.
// ---------------------------------------------------------------------------
__device__ __forceinline__ void gemm_mainloop(const float* __restrict__ A, int lda,
                                              const float* __restrict__ B, int ldb,
                                              int kStart, int nk, float* smem,
                                              float acc[4][8][4], int tid) {
    const int lane = tid & 31, warp = tid >> 5;
    const int wm = warp >> 1, wn = warp & 1;
    const uint32_t s0 = smem_u32(smem);

    const int q = lane >> 3, qr = lane & 7;
    uint32_t aoff[4], boff[4];
#pragma unroll
    for (int mt = 0; mt < 4; mt++)
        aoff[mt] = (uint32_t)(((wm * 64 + mt * 16 + (q & 1) * 8 + qr) * PADK + (q >> 1) * 4) * 4);
#pragma unroll
    for (int p = 0; p < 4; p++)
        boff[p] = (uint32_t)(((wn * 64 + p * 16 + ((q >> 1) & 1) * 8 + qr) * PADK + (q & 1) * 4) * 4);

#pragma unroll
    for (int s = 0; s < NSTAGE - 1; s++) {
        if (s < nk) {
            const uint32_t sb = s0 + (uint32_t)s * BUF_BYTES;
            stage_cp(A, lda, kStart + s * BK, sb, tid);
            stage_cp(B, ldb, kStart + s * BK, sb + TILE_BYTES, tid);
        }
        CP_COMMIT();
    }

    for (int i = 0; i < nk; i++) {
        CP_WAIT(NSTAGE - 2);
        __syncthreads();
        if (i + NSTAGE - 1 < nk) {
            const int s = (i + NSTAGE - 1) % NSTAGE;
            const uint32_t sb = s0 + (uint32_t)s * BUF_BYTES;
            stage_cp(A, lda, kStart + (i + NSTAGE - 1) * BK, sb, tid);
            stage_cp(B, ldb, kStart + (i + NSTAGE - 1) * BK, sb + TILE_BYTES, tid);
        }
        CP_COMMIT();
        const uint32_t sA = s0 + (uint32_t)(i % NSTAGE) * BUF_BYTES;
        compute_chunk(sA, sA + TILE_BYTES, aoff, boff, acc);
    }
}

// Epilogue coords: row0 = wm*64+mt*16+(lane>>2), row1=row0+8;
//                  col = wn*64+nt*8+(lane&3)*2

// ---------------------------------------------------------------------------
// GEMM 1 (split): qkv[:, colBase:...] = xr @ WT^T + b; skips all-padding rows
// ---------------------------------------------------------------------------
__global__ __launch_bounds__(NT, 2) void k_qkv_tc(const float* __restrict__ bias,
                                                  const int* __restrict__ npadd_p,
                                                  int colBase) {
    extern __shared__ float smem[];
    const int tid = threadIdx.x;
    const int bx = blockIdx.x, by = blockIdx.y;
    if ((by + 1) * BM <= *npadd_p) return;
    float acc[4][8][4] = {};
    gemm_mainloop(g_xr + (size_t)by * BM * CIN, CIN,
                  g_WT + (size_t)(colBase + bx * BN) * CIN, CIN, 0, CIN / BK, smem, acc, tid);

    const int lane = tid & 31, warp = tid >> 5;
    const int wm = warp >> 1, wn = warp & 1;
#pragma unroll
    for (int mt = 0; mt < 4; mt++) {
        const int r0 = by * BM + wm * 64 + mt * 16 + (lane >> 2);
#pragma unroll
        for (int nt = 0; nt < 8; nt++) {
            const int col = colBase + bx * BN + wn * 64 + nt * 8 + (lane & 3) * 2;
            const float b0 = bias[col], b1 = bias[col + 1];
            *(float2*)(g_qkv + (size_t)r0 * QKVN + col) =
                make_float2(rnd_tf32(acc[mt][nt][0] + b0), rnd_tf32(acc[mt][nt][1] + b1));
            *(float2*)(g_qkv + (size_t)(r0 + 8) * QKVN + col) =
                make_float2(rnd_tf32(acc[mt][nt][2] + b0), rnd_tf32(acc[mt][nt][3] + b1));
        }
    }
}

// ---------------------------------------------------------------------------
// GEMM 2: att = mask(q @ k^T * scale)  grid (32, 32)
// ---------------------------------------------------------------------------
__global__ __launch_bounds__(NT, 2) void k_att_tc(const int* __restrict__ npadd_p) {
    extern __shared__ float smem[];
    const int tid = threadIdx.x;
    const int bx = blockIdx.x, by = blockIdx.y;
    if (bx > by) return;
    const int n_padd = *npadd_p;
    const int rowMax = by * BM + BM - 1;
    const int colMin = bx * BN, colMax = colMin + BN - 1;
    if (rowMax < n_padd) return;
    if (colMax < n_padd) {
        const float4 negv = make_float4(NEGV, NEGV, NEGV, NEGV);
        for (int i = tid; i < BM * BN / 4; i += NT) {
            int m = i >> 5, n = (i & 31) << 2;
            *(float4*)(g_att + (size_t)(by * BM + m) * TSEQ + colMin + n) = negv;
        }
        return;
    }

    float acc[4][8][4] = {};
    gemm_mainloop(g_qkv + (size_t)by * BM * QKVN, QKVN,
                  g_qkv + (size_t)bx * BN * QKVN + NF, QKVN, 0, NF / BK, smem, acc, tid);

    const float scale = 0.022097086912079608f;  // 1/sqrt(2048)
    const int lane = tid & 31, warp = tid >> 5;
    const int wm = warp >> 1, wn = warp & 1;
#pragma unroll
    for (int mt = 0; mt < 4; mt++) {
        const int r0 = by * BM + wm * 64 + mt * 16 + (lane >> 2);
        const int r1 = r0 + 8;
#pragma unroll
        for (int nt = 0; nt < 8; nt++) {
            const int col = bx * BN + wn * 64 + nt * 8 + (lane & 3) * 2;
            float2 o0, o1;
            o0.x = (r0 >= n_padd && col     <= r0 && col     >= n_padd) ? acc[mt][nt][0] * scale : NEGV;
            o0.y = (r0 >= n_padd && col + 1 <= r0 && col + 1 >= n_padd) ? acc[mt][nt][1] * scale : NEGV;
            o1.x = (r1 >= n_padd && col     <= r1 && col     >= n_padd) ? acc[mt][nt][2] * scale : NEGV;
            o1.y = (r1 >= n_padd && col + 1 <= r1 && col + 1 >= n_padd) ? acc[mt][nt][3] * scale : NEGV;
            *(float2*)(g_att + (size_t)r0 * TSEQ + col) = o0;
            *(float2*)(g_att + (size_t)r1 * TSEQ + col) = o1;
        }
    }
}

// ---------------------------------------------------------------------------
// GEMM 3: y = p @ vT^T   grid (16, 32); K in [n_padd&~31, (by+1)*128)
// ---------------------------------------------------------------------------
__global__ __launch_bounds__(NT, 2) void k_out_tc(float* __restrict__ Y,
                                                  const int* __restrict__ npadd_p) {
    extern __shared__ float smem[];
    const int tid = threadIdx.x;
    const int bx = blockIdx.x;
    const int by = (gridDim.y - 1) - blockIdx.y;    // heavy first
    const int n_padd = *npadd_p;
    const int kStart = n_padd & ~(BK - 1);
    const int nk = ((by + 1) * BM - kStart) / BK;

    if (nk <= 0) {
        const float4 z = make_float4(0.f, 0.f, 0.f, 0.f);
        for (int i = tid; i < BM * BN / 4; i += NT) {
            int m = i >> 5, n = (i & 31) << 2;
            *(float4*)(Y + (size_t)(by * BM + m) * NF + bx * BN + n) = z;
        }
        return;
    }

    float acc[4][8][4] = {};
    gemm_mainloop(g_att + (size_t)by * BM * TSEQ, TSEQ,
                  g_vT + (size_t)bx * BN * TSEQ, TSEQ, kStart, nk, smem, acc, tid);

    const int lane = tid & 31, warp = tid >> 5;
    const int wm = warp >> 1, wn = warp & 1;
#pragma unroll
    for (int mt = 0; mt < 4; mt++) {
        const int r0 = by * BM + wm * 64 + mt * 16 + (lane >> 2);
#pragma unroll
        for (int nt = 0; nt < 8; nt++) {
            const int col = bx * BN + wn * 64 + nt * 8 + (lane & 3) * 2;
            *(float2*)(Y + (size_t)r0 * NF + col) =
                make_float2(acc[mt][nt][0], acc[mt][nt][1]);
            *(float2*)(Y + (size_t)(r0 + 8) * NF + col) =
                make_float2(acc[mt][nt][2], acc[mt][nt][3]);
        }
    }
}

// ---------------------------------------------------------------------------
// Transpose + round: dst[c][r] = tf32(src[r][c])
// ---------------------------------------------------------------------------
__global__ void k_transpose(const float* __restrict__ src, float* __restrict__ dst,
                            int lds, int ldd) {
    __shared__ float t[32][33];
    const int bx = blockIdx.x * 32, by = blockIdx.y * 32;
    const int x = threadIdx.x, y = threadIdx.y;
#pragma unroll
    for (int j = 0; j < 32; j += 8)
        t[y + j][x] = rnd_tf32(src[(size_t)(by + y + j) * lds + bx + x]);
    __syncthreads();
#pragma unroll
    for (int j = 0; j < 32; j += 8)
        dst[(size_t)(bx + y + j) * ldd + by + x] = t[x][y + j];
}

// Round-copy: g_xr = tf32(x)
__global__ void k_roundcpy(const float* __restrict__ src, float* __restrict__ dst, int n4) {
    int i = blockIdx.x * blockDim.x + threadIdx.x;
    if (i < n4) {
        float4 v = ((const float4*)src)[i];
        v.x = rnd_tf32(v.x); v.y = rnd_tf32(v.y);
        v.z = rnd_tf32(v.z); v.w = rnd_tf32(v.w);
        ((float4*)dst)[i] = v;
    }
}

// ---------------------------------------------------------------------------
// Row softmax over the causal prefix [0, cap), cap = ceil128(r+1).
// ---------------------------------------------------------------------------
__global__ __launch_bounds__(256) void k_softmax(const int* __restrict__ npadd_p) {
    const int r = blockIdx.x;
    const int n_padd = *npadd_p;
    const int cap = ((r >> 7) + 1) << 7;       // multiple of 128, > r
    float* row = g_att + (size_t)r * TSEQ;
    const int tid = threadIdx.x;
    if (r < n_padd) {
        for (int c = tid * 4; c < cap; c += 256 * 4)
            *(float4*)(row + c) = make_float4(0.f, 0.f, 0.f, 0.f);
        return;
    }
    __shared__ float redmax[8], redsum[8];
    float vals[16];
    float mx = NEGV;
#pragma unroll
    for (int i = 0; i < 16; i++) {
        const int c = tid + i * 256;
        vals[i] = (c < cap) ? row[c] : NEGV;
        mx = fmaxf(mx, vals[i]);
    }
#pragma unroll
    for (int o = 16; o > 0; o >>= 1) mx = fmaxf(mx, __shfl_xor_sync(0xffffffffu, mx, o));
    if ((tid & 31) == 0) redmax[tid >> 5] = mx;
    __syncthreads();
    mx = redmax[0];
#pragma unroll
    for (int i = 1; i < 8; i++) mx = fmaxf(mx, redmax[i]);
    float s = 0.f;
#pragma unroll
    for (int i = 0; i < 16; i++) {
        vals[i] = __expf(vals[i] - mx);    // underflows to 0 for masked entries
        s += vals[i];
    }
#pragma unroll
    for (int o = 16; o > 0; o >>= 1) s += __shfl_xor_sync(0xffffffffu, s, o);
    if ((tid & 31) == 0) redsum[tid >> 5] = s;
    __syncthreads();
    s = redsum[0];
#pragma unroll
    for (int i = 1; i < 8; i++) s += redsum[i];
    const float inv = 1.f / s;
#pragma unroll
    for (int i = 0; i < 16; i++) {
        const int c = tid + i * 256;
        if (c < cap) row[c] = rnd_tf32(vals[i] * inv);
    }
}

// ---------------------------------------------------------------------------
extern "C" void kernel_launch(void* const* d_in, const int* in_sizes, int n_in,
                              void* d_out, int out_size) {
    const float* x  = (const float*)d_in[0];
    const float* W  = (const float*)d_in[1];
    const float* b  = (const float*)d_in[2];
    const int* npad = (const int*)d_in[3];
    float* y = (float*)d_out;

    cudaFuncSetAttribute(k_qkv_tc, cudaFuncAttributeMaxDynamicSharedMemorySize, DYN_SMEM);
    cudaFuncSetAttribute(k_att_tc, cudaFuncAttributeMaxDynamicSharedMemorySize, DYN_SMEM);
    cudaFuncSetAttribute(k_out_tc, cudaFuncAttributeMaxDynamicSharedMemorySize, DYN_SMEM);

    // One-time stream/event creation (host-side only; no device allocation).
    static cudaStream_t sV = nullptr;
    static cudaEvent_t evFork = nullptr, evJoin = nullptr;
    if (sV == nullptr) {
        cudaStreamCreateWithFlags(&sV, cudaStreamNonBlocking);
        cudaEventCreateWithFlags(&evFork, cudaEventDisableTiming);
        cudaEventCreateWithFlags(&evJoin, cudaEventDisableTiming);
    }

    float *wt_p, *vt_p, *qkv_p, *xr_p;
    cudaGetSymbolAddress((void**)&wt_p, g_WT);
    cudaGetSymbolAddress((void**)&vt_p, g_vT);
    cudaGetSymbolAddress((void**)&qkv_p, g_qkv);
    cudaGetSymbolAddress((void**)&xr_p, g_xr);

    dim3 tb(32, 8);
    const int nx4 = TSEQ * CIN / 4;
    const cudaStream_t s0 = 0;

    // Main stream: round x, transpose W (capture-legal: side stream joins
    // only via StreamWaitEvent on an event recorded in the capturing stream).
    k_roundcpy<<<(nx4 + 255) / 256, 256, 0, s0>>>(x, xr_p, nx4);
    k_transpose<<<dim3(QKVN / 32, CIN / 32), tb, 0, s0>>>(W, wt_p, QKVN, CIN);
    cudaEventRecord(evFork, s0);

    // Side stream: v-columns of qkv + v transpose (needed only by k_out)
    cudaStreamWaitEvent(sV, evFork, 0);
    k_qkv_tc<<<dim3((QKVN - 2 * NF) / BN, TSEQ / BM), NT, DYN_SMEM, sV>>>(b, npad, 2 * NF);
    k_transpose<<<dim3(NF / 32, TSEQ / 32), tb, 0, sV>>>(qkv_p + 2 * NF, vt_p, QKVN, TSEQ);
    cudaEventRecord(evJoin, sV);

    // Main stream: qk-columns, att, softmax
    k_qkv_tc<<<dim3(2 * NF / BN, TSEQ / BM), NT, DYN_SMEM, s0>>>(b, npad, 0);
    k_att_tc<<<dim3(TSEQ / BN, TSEQ / BM), NT, DYN_SMEM, s0>>>(npad);
    k_softmax<<<TSEQ, 256, 0, s0>>>(npad);

    // Join: k_out needs vT
    cudaStreamWaitEvent(s0, evJoin, 0);
    k_out_tc<<<dim3(NF / BN, TSEQ / BM), NT, DYN_SMEM, s0>>>(y, npad);
}